// round 4
// baseline (speedup 1.0000x reference)
#include <cuda_runtime.h>
#include <math.h>

// SpectralEMA.  state_t = a*|state_{t-1}|*unit(x_t) + (1-rho)*x_t
//             = x_t * z_t / w_t,  z_t = a*m_{t-1} + omr*w_t,  m_t = |z_t|
// Real a (theta=0): m_t = rho*m_{t-1} + omr*w_t  -> affine scan; segments
// compose: m_out = rho^L * m_in + C_seg.
// Phase 1: G parallel segments per chain compute C (float4 = 4 features/thread).
// Phase 2: combine segments (1 feature/thread), reconstruct from x[S-1].

#define G   16
#define UNR 4
#define MAX_BF (32 * 4096)

__device__ float g_C[G * MAX_BF];

__device__ __forceinline__ float sigmoidf_(float x) {
    return 1.0f / (1.0f + expf(-x));
}

// ---------------- Phase 1: per-segment affine coefficient C ----------------
__global__ __launch_bounds__(256)
void phase1_kernel(const float* __restrict__ fr, const float* __restrict__ fi,
                   const float* __restrict__ rho_logit,
                   int S, int F, int L)
{
    int F4 = F >> 2;
    int f4 = blockIdx.x * blockDim.x + threadIdx.x;
    if (f4 >= F4) return;
    int b = blockIdx.y;
    int g = blockIdx.z;

    float4 rl = __ldg((const float4*)rho_logit + f4);
    float rho0 = sigmoidf_(rl.x), rho1 = sigmoidf_(rl.y);
    float rho2 = sigmoidf_(rl.z), rho3 = sigmoidf_(rl.w);
    float om0 = 1.0f - rho0, om1 = 1.0f - rho1;
    float om2 = 1.0f - rho2, om3 = 1.0f - rho3;

    size_t base = ((size_t)b * (size_t)S + (size_t)g * (size_t)L) * (size_t)F
                + (size_t)(f4 << 2);
    const float4* pr  = (const float4*)(fr + base);
    const float4* pim = (const float4*)(fi + base);
    size_t st = (size_t)F4;                 // float4 stride per step

    float C0 = 0.0f, C1 = 0.0f, C2 = 0.0f, C3 = 0.0f;

    int nch = L / UNR;
    float4 cr[UNR], ci[UNR];
#pragma unroll
    for (int k = 0; k < UNR; ++k) {
        cr[k] = __ldcs(pr  + (size_t)k * st);
        ci[k] = __ldcs(pim + (size_t)k * st);
    }
    pr  += (size_t)UNR * st;
    pim += (size_t)UNR * st;

#pragma unroll 1
    for (int j = 0; j < nch; ++j) {
        float4 nr[UNR], ni[UNR];
        if (j + 1 < nch) {
#pragma unroll
            for (int k = 0; k < UNR; ++k) {
                nr[k] = __ldcs(pr  + (size_t)k * st);
                ni[k] = __ldcs(pim + (size_t)k * st);
            }
            pr  += (size_t)UNR * st;
            pim += (size_t)UNR * st;
        }
#pragma unroll
        for (int k = 0; k < UNR; ++k) {
            float w0 = sqrtf(fmaxf(fmaf(cr[k].x, cr[k].x, ci[k].x * ci[k].x), 1e-37f));
            float w1 = sqrtf(fmaxf(fmaf(cr[k].y, cr[k].y, ci[k].y * ci[k].y), 1e-37f));
            float w2 = sqrtf(fmaxf(fmaf(cr[k].z, cr[k].z, ci[k].z * ci[k].z), 1e-37f));
            float w3 = sqrtf(fmaxf(fmaf(cr[k].w, cr[k].w, ci[k].w * ci[k].w), 1e-37f));
            C0 = fmaf(rho0, C0, om0 * w0);
            C1 = fmaf(rho1, C1, om1 * w1);
            C2 = fmaf(rho2, C2, om2 * w2);
            C3 = fmaf(rho3, C3, om3 * w3);
        }
#pragma unroll
        for (int k = 0; k < UNR; ++k) { cr[k] = nr[k]; ci[k] = ni[k]; }
    }

    size_t bf0 = (size_t)b * (size_t)F + (size_t)(f4 << 2);
    float4* cdst = (float4*)(g_C + (size_t)g * MAX_BF + bf0);
    *cdst = make_float4(C0, C1, C2, C3);
}

// ---------------- Phase 2: combine segments, write output ----------------
__global__ __launch_bounds__(256)
void phase2_kernel(const float* __restrict__ fr, const float* __restrict__ fi,
                   const float* __restrict__ ir, const float* __restrict__ ii,
                   const float* __restrict__ rho_logit,
                   const float* __restrict__ theta_raw,
                   float2* __restrict__ out, int S, int F, int L)
{
    int f = blockIdx.x * blockDim.x + threadIdx.x;
    if (f >= F) return;
    int b = blockIdx.y;
    size_t bf = (size_t)b * (size_t)F + (size_t)f;

    float rho = sigmoidf_(__ldg(rho_logit + f));
    float thw = __ldg(theta_raw + f);

    float sr = __ldg(ir + bf), si = __ldg(ii + bf);
    float m = sqrtf(fmaxf(fmaf(sr, sr, si * si), 1e-37f));

    // last-step input (already hot in L2 from phase1's tail segment)
    size_t last = ((size_t)b * (size_t)S + (size_t)(S - 1)) * (size_t)F + (size_t)f;
    float lxr = __ldg(fr + last);
    float lxi = __ldg(fi + last);

    if (thw == 0.0f) {
        float D = __powf(rho, (float)L);
#pragma unroll
        for (int g = 0; g < G; ++g)
            m = fmaf(D, m, __ldg(g_C + (size_t)g * MAX_BF + bf));
        // m == z_last (real, >= 0).  out = x_last * m / w_last
        float w2 = fmaxf(fmaf(lxr, lxr, lxi * lxi), 1e-37f);
        float s  = m * rsqrtf(w2);
        out[bf] = make_float2(lxr * s, lxi * s);
    } else {
        // general complex-a path (not taken for this dataset): full rescan
        float th = 3.14159265358979323846f * tanhf(thw);
        float ss, sc;
        sincosf(th, &ss, &sc);
        float ar = rho * sc, ai = rho * ss, omr = 1.0f - rho;
        const float* p  = fr + (size_t)b * (size_t)S * (size_t)F + f;
        const float* pi = fi + (size_t)b * (size_t)S * (size_t)F + f;
        float zr = 0.f, zi = 0.f, rinv = 1.f, lr = 0.f, li = 0.f;
        for (int s = 0; s < S; ++s) {
            float xr = __ldcs(p), xi = __ldcs(pi);
            p += F; pi += F;
            float x2 = fmaxf(fmaf(xr, xr, xi * xi), 1e-37f);
            float rv = rsqrtf(x2);
            float w  = x2 * rv;
            zr = fmaf(ar, m, omr * w);
            zi = ai * m;
            float z2 = fmaxf(fmaf(zr, zr, zi * zi), 1e-37f);
            m = z2 * rsqrtf(z2);
            rinv = rv; lr = xr; li = xi;
        }
        out[bf] = make_float2((zr * lr - zi * li) * rinv,
                              fmaf(zr, li, zi * lr) * rinv);
    }
}

// ---------------- Monolithic fallback (unexpected shapes) ----------------
__global__ __launch_bounds__(256)
void mono_kernel(const float* __restrict__ fr, const float* __restrict__ fi,
                 const float* __restrict__ ir, const float* __restrict__ ii,
                 const float* __restrict__ rho_logit,
                 const float* __restrict__ theta_raw,
                 float2* __restrict__ out, int S, int F)
{
    int f = blockIdx.x * blockDim.x + threadIdx.x;
    if (f >= F) return;
    int b = blockIdx.y;
    size_t bf = (size_t)b * (size_t)F + (size_t)f;

    float rho = sigmoidf_(rho_logit[f]);
    float th  = 3.14159265358979323846f * tanhf(theta_raw[f]);
    float ss, sc;
    sincosf(th, &ss, &sc);
    float ar = rho * sc, ai = rho * ss, omr = 1.0f - rho;

    float srv = ir[bf], siv = ii[bf];
    float m = sqrtf(fmaxf(fmaf(srv, srv, siv * siv), 1e-37f));

    const float* pr  = fr + (size_t)b * (size_t)S * (size_t)F + f;
    const float* pim = fi + (size_t)b * (size_t)S * (size_t)F + f;
    float zr = 0.f, zi = 0.f, rinv = 1.f, lxr = 0.f, lxi = 0.f;
    for (int s = 0; s < S; ++s) {
        float xr = __ldcs(pr), xi = __ldcs(pim);
        pr += F; pim += F;
        float x2 = fmaxf(fmaf(xr, xr, xi * xi), 1e-37f);
        float rv = rsqrtf(x2);
        float w  = x2 * rv;
        zr = fmaf(ar, m, omr * w);
        zi = ai * m;
        float z2 = fmaxf(fmaf(zr, zr, zi * zi), 1e-37f);
        m = z2 * rsqrtf(z2);
        rinv = rv; lxr = xr; lxi = xi;
    }
    out[bf] = make_float2((zr * lxr - zi * lxi) * rinv,
                          fmaf(zr, lxi, zi * lxr) * rinv);
}

extern "C" void kernel_launch(void* const* d_in, const int* in_sizes, int n_in,
                              void* d_out, int out_size)
{
    const float* fr = (const float*)d_in[0];
    const float* fi = (const float*)d_in[1];
    const float* ir = (const float*)d_in[2];
    const float* ii = (const float*)d_in[3];
    const float* rl = (const float*)d_in[4];
    const float* tr = (const float*)d_in[5];

    int F  = in_sizes[4];
    int BF = in_sizes[2];
    int B  = BF / F;
    int S  = in_sizes[0] / BF;

    dim3 block(256);

    bool fast = (BF <= MAX_BF) && (F % 1024 == 0) && (S % (G * UNR) == 0);
    if (fast) {
        int L  = S / G;
        int F4 = F / 4;
        dim3 grid1(F4 / 256, B, G);
        phase1_kernel<<<grid1, block>>>(fr, fi, rl, S, F, L);
        dim3 grid2((F + 255) / 256, B);
        phase2_kernel<<<grid2, block>>>(fr, fi, ir, ii, rl, tr,
                                        (float2*)d_out, S, F, L);
    } else {
        dim3 grid((F + 255) / 256, B);
        mono_kernel<<<grid, block>>>(fr, fi, ir, ii, rl, tr,
                                     (float2*)d_out, S, F);
    }
}

// round 5
// speedup vs baseline: 1.2294x; 1.2294x over previous
#include <cuda_runtime.h>
#include <math.h>

// SpectralEMA.  state_t = a*|state_{t-1}|*unit(x_t) + (1-rho)*x_t
//             = x_t * z_t / w_t,  z_t = a*m_{t-1} + omr*w_t,  m_t = |z_t|
// Real a (theta=0): m_t = rho*m_{t-1} + omr*w_t  -> affine scan; segments
// compose: m_out = rho^L * m_in + C_seg.
// Phase 1: G parallel segments per chain compute C (float2 = 2 features/thread,
//          the empirically optimal load shape on this chip).
// Phase 2: combine segments (1 feature/thread), reconstruct from stored x_last.

#define G   16
#define UNR 4
#define MAX_BF (32 * 4096)

__device__ float  g_C[G * MAX_BF];
__device__ float2 g_lx[MAX_BF];   // (xr, xi) at s = S-1 per chain

__device__ __forceinline__ float sigmoidf_(float x) {
    return 1.0f / (1.0f + expf(-x));
}

// |v| via single MUFU.RSQ: |v| = v2 * rsqrt(v2)
__device__ __forceinline__ float mag_(float vr, float vi) {
    float v2 = fmaxf(fmaf(vr, vr, vi * vi), 1e-37f);
    return v2 * rsqrtf(v2);
}

// ---------------- Phase 1: per-segment affine coefficient C ----------------
__global__ __launch_bounds__(256)
void phase1_kernel(const float* __restrict__ fr, const float* __restrict__ fi,
                   const float* __restrict__ rho_logit,
                   int S, int F, int L)
{
    int F2 = F >> 1;
    int f2 = blockIdx.x * blockDim.x + threadIdx.x;
    if (f2 >= F2) return;
    int b = blockIdx.y;
    int g = blockIdx.z;

    float2 rl  = __ldg((const float2*)rho_logit + f2);
    float rho0 = sigmoidf_(rl.x), rho1 = sigmoidf_(rl.y);
    float om0  = 1.0f - rho0,     om1  = 1.0f - rho1;

    size_t base = ((size_t)b * (size_t)S + (size_t)g * (size_t)L) * (size_t)F
                + (size_t)(f2 << 1);
    const float2* pr  = (const float2*)(fr + base);
    const float2* pim = (const float2*)(fi + base);
    size_t st = (size_t)F2;              // float2 stride per step

    float C0 = 0.0f, C1 = 0.0f;
    float2 lxr = make_float2(0.f, 0.f), lxi = make_float2(0.f, 0.f);

    int nch = L / UNR;
    float2 cr[UNR], ci[UNR];
#pragma unroll
    for (int k = 0; k < UNR; ++k) {
        cr[k] = __ldcs(pr  + (size_t)k * st);
        ci[k] = __ldcs(pim + (size_t)k * st);
    }
    pr  += (size_t)UNR * st;
    pim += (size_t)UNR * st;

#pragma unroll 1
    for (int j = 0; j < nch; ++j) {
        float2 nr[UNR], ni[UNR];
        if (j + 1 < nch) {
#pragma unroll
            for (int k = 0; k < UNR; ++k) {
                nr[k] = __ldcs(pr  + (size_t)k * st);
                ni[k] = __ldcs(pim + (size_t)k * st);
            }
            pr  += (size_t)UNR * st;
            pim += (size_t)UNR * st;
        }
#pragma unroll
        for (int k = 0; k < UNR; ++k) {
            float wa = mag_(cr[k].x, ci[k].x);
            float wb = mag_(cr[k].y, ci[k].y);
            C0 = fmaf(rho0, C0, om0 * wa);
            C1 = fmaf(rho1, C1, om1 * wb);
            lxr = cr[k]; lxi = ci[k];
        }
#pragma unroll
        for (int k = 0; k < UNR; ++k) { cr[k] = nr[k]; ci[k] = ni[k]; }
    }

    size_t bf0 = (size_t)b * (size_t)F + (size_t)(f2 << 1);
    *(float2*)(g_C + (size_t)g * MAX_BF + bf0) = make_float2(C0, C1);
    if (g == G - 1) {
        g_lx[bf0]     = make_float2(lxr.x, lxi.x);
        g_lx[bf0 + 1] = make_float2(lxr.y, lxi.y);
    }
}

// ---------------- Phase 2: combine segments, write output ----------------
__global__ __launch_bounds__(256)
void phase2_kernel(const float* __restrict__ fr, const float* __restrict__ fi,
                   const float* __restrict__ ir, const float* __restrict__ ii,
                   const float* __restrict__ rho_logit,
                   const float* __restrict__ theta_raw,
                   float2* __restrict__ out, int S, int F, int L)
{
    int f = blockIdx.x * blockDim.x + threadIdx.x;
    if (f >= F) return;
    int b = blockIdx.y;
    size_t bf = (size_t)b * (size_t)F + (size_t)f;

    float rho = sigmoidf_(__ldg(rho_logit + f));
    float thw = __ldg(theta_raw + f);

    float sr = __ldg(ir + bf), si = __ldg(ii + bf);
    float m = mag_(sr, si);

    if (thw == 0.0f) {
        float D = __powf(rho, (float)L);
        // 16 independent coalesced loads (MLP=16), then a short FMA chain
        float c[G];
#pragma unroll
        for (int g = 0; g < G; ++g)
            c[g] = __ldg(g_C + (size_t)g * MAX_BF + bf);
        float2 lx = g_lx[bf];
#pragma unroll
        for (int g = 0; g < G; ++g)
            m = fmaf(D, m, c[g]);
        // m == z_last (real, >= 0).  out = x_last * m / |x_last|
        float w2 = fmaxf(fmaf(lx.x, lx.x, lx.y * lx.y), 1e-37f);
        float s  = m * rsqrtf(w2);
        out[bf] = make_float2(lx.x * s, lx.y * s);
    } else {
        // general complex-a path (not taken for this dataset): full rescan
        float th = 3.14159265358979323846f * tanhf(thw);
        float ss, sc;
        sincosf(th, &ss, &sc);
        float ar = rho * sc, ai = rho * ss, omr = 1.0f - rho;
        const float* p  = fr + (size_t)b * (size_t)S * (size_t)F + f;
        const float* pi = fi + (size_t)b * (size_t)S * (size_t)F + f;
        float zr = 0.f, zi = 0.f, rinv = 1.f, lr = 0.f, li = 0.f;
        for (int s = 0; s < S; ++s) {
            float xr = __ldcs(p), xi = __ldcs(pi);
            p += F; pi += F;
            float x2 = fmaxf(fmaf(xr, xr, xi * xi), 1e-37f);
            float rv = rsqrtf(x2);
            float w  = x2 * rv;
            zr = fmaf(ar, m, omr * w);
            zi = ai * m;
            m = mag_(zr, zi);
            rinv = rv; lr = xr; li = xi;
        }
        out[bf] = make_float2((zr * lr - zi * li) * rinv,
                              fmaf(zr, li, zi * lr) * rinv);
    }
}

// ---------------- Monolithic fallback (unexpected shapes) ----------------
__global__ __launch_bounds__(256)
void mono_kernel(const float* __restrict__ fr, const float* __restrict__ fi,
                 const float* __restrict__ ir, const float* __restrict__ ii,
                 const float* __restrict__ rho_logit,
                 const float* __restrict__ theta_raw,
                 float2* __restrict__ out, int S, int F)
{
    int f = blockIdx.x * blockDim.x + threadIdx.x;
    if (f >= F) return;
    int b = blockIdx.y;
    size_t bf = (size_t)b * (size_t)F + (size_t)f;

    float rho = sigmoidf_(rho_logit[f]);
    float th  = 3.14159265358979323846f * tanhf(theta_raw[f]);
    float ss, sc;
    sincosf(th, &ss, &sc);
    float ar = rho * sc, ai = rho * ss, omr = 1.0f - rho;

    float srv = ir[bf], siv = ii[bf];
    float m = mag_(srv, siv);

    const float* pr  = fr + (size_t)b * (size_t)S * (size_t)F + f;
    const float* pim = fi + (size_t)b * (size_t)S * (size_t)F + f;
    float zr = 0.f, zi = 0.f, rinv = 1.f, lxr = 0.f, lxi = 0.f;
    for (int s = 0; s < S; ++s) {
        float xr = __ldcs(pr), xi = __ldcs(pim);
        pr += F; pim += F;
        float x2 = fmaxf(fmaf(xr, xr, xi * xi), 1e-37f);
        float rv = rsqrtf(x2);
        float w  = x2 * rv;
        zr = fmaf(ar, m, omr * w);
        zi = ai * m;
        m = mag_(zr, zi);
        rinv = rv; lxr = xr; lxi = xi;
    }
    out[bf] = make_float2((zr * lxr - zi * lxi) * rinv,
                          fmaf(zr, lxi, zi * lxr) * rinv);
}

extern "C" void kernel_launch(void* const* d_in, const int* in_sizes, int n_in,
                              void* d_out, int out_size)
{
    const float* fr = (const float*)d_in[0];
    const float* fi = (const float*)d_in[1];
    const float* ir = (const float*)d_in[2];
    const float* ii = (const float*)d_in[3];
    const float* rl = (const float*)d_in[4];
    const float* tr = (const float*)d_in[5];

    int F  = in_sizes[4];
    int BF = in_sizes[2];
    int B  = BF / F;
    int S  = in_sizes[0] / BF;

    dim3 block(256);

    bool fast = (BF <= MAX_BF) && (F % 512 == 0) && (S % (G * UNR) == 0);
    if (fast) {
        int L  = S / G;
        int F2 = F / 2;
        dim3 grid1(F2 / 256, B, G);
        phase1_kernel<<<grid1, block>>>(fr, fi, rl, S, F, L);
        dim3 grid2((F + 255) / 256, B);
        phase2_kernel<<<grid2, block>>>(fr, fi, ir, ii, rl, tr,
                                        (float2*)d_out, S, F, L);
    } else {
        dim3 grid((F + 255) / 256, B);
        mono_kernel<<<grid, block>>>(fr, fi, ir, ii, rl, tr,
                                     (float2*)d_out, S, F);
    }
}